// round 4
// baseline (speedup 1.0000x reference)
#include <cuda_runtime.h>
#include <cuda_bf16.h>
#include <cstdint>

#define N_SEL   192
#define N_PTS   2048
#define C_IN    256
#define C_OUT   256
#define N_TILES 8

#define BM 128
#define BN 128
#define BK 32
#define NSLABS (C_IN / BK)   // 8

#define ROWB   80            // bf16 tile row bytes: 32*2 + 16 pad
#define ARAWB  144           // raw fp32 A row bytes: 32*4 + 16 pad

// dynamic smem layout
#define SM_BIAS    0
#define SM_AH      1024
#define SM_AL      (SM_AH + BM * ROWB)          // 11264
#define SM_ARAW    (SM_AL + BM * ROWB)          // 21504
#define ARAW_STG   (BM * ARAWB)                 // 18432
#define SM_BH      (SM_ARAW + 2 * ARAW_STG)     // 58368
#define B_STG      (BN * ROWB)                  // 10240
#define SM_BL      (SM_BH + 2 * B_STG)          // 78848
#define SM_TOTAL   (SM_BL + 2 * B_STG)          // 99328

// gathered, transposed, bf16-split weights: [n_sel][N=C_OUT][K=C_IN]
__device__ __nv_bfloat16 g_wt_h[(size_t)N_SEL * C_OUT * C_IN];
__device__ __nv_bfloat16 g_wt_l[(size_t)N_SEL * C_OUT * C_IN];

__device__ __forceinline__ uint32_t smem_u32(const void* p) {
    uint32_t a;
    asm("{ .reg .u64 t; cvta.to.shared.u64 t, %1; cvt.u32.u64 %0, t; }" : "=r"(a) : "l"(p));
    return a;
}
__device__ __forceinline__ void cp16(uint32_t dst, const void* src) {
    asm volatile("cp.async.cg.shared.global [%0], [%1], 16;" :: "r"(dst), "l"(src));
}
__device__ __forceinline__ void bf16_split2(float a, float b, uint32_t& h, uint32_t& l) {
    __nv_bfloat16 ha = __float2bfloat16_rn(a);
    __nv_bfloat16 hb = __float2bfloat16_rn(b);
    __nv_bfloat16 la = __float2bfloat16_rn(a - __bfloat162float(ha));
    __nv_bfloat16 lb = __float2bfloat16_rn(b - __bfloat162float(hb));
    h = (uint32_t)__bfloat16_as_ushort(ha) | ((uint32_t)__bfloat16_as_ushort(hb) << 16);
    l = (uint32_t)__bfloat16_as_ushort(la) | ((uint32_t)__bfloat16_as_ushort(lb) << 16);
}
__device__ __forceinline__ void ldmx4(uint32_t addr, uint32_t& r0, uint32_t& r1,
                                      uint32_t& r2, uint32_t& r3) {
    asm volatile("ldmatrix.sync.aligned.m8n8.x4.shared.b16 {%0,%1,%2,%3}, [%4];"
                 : "=r"(r0), "=r"(r1), "=r"(r2), "=r"(r3) : "r"(addr));
}
__device__ __forceinline__ void mma_bf16(float* c, const uint32_t* a, const uint32_t* b) {
    asm volatile("mma.sync.aligned.m16n8k16.row.col.f32.bf16.bf16.f32 "
                 "{%0,%1,%2,%3}, {%4,%5,%6,%7}, {%8,%9}, {%0,%1,%2,%3};"
                 : "+f"(c[0]), "+f"(c[1]), "+f"(c[2]), "+f"(c[3])
                 : "r"(a[0]), "r"(a[1]), "r"(a[2]), "r"(a[3]), "r"(b[0]), "r"(b[1]));
}

// ---------------- kernel 1: gather + transpose + bf16 split of W ----------------
__global__ void wt_prep_kernel(const float* __restrict__ weight,
                               const int* __restrict__ indices,
                               const int* __restrict__ t_ptr) {
    const int n = blockIdx.z;
    const int t = (t_ptr != nullptr) ? *t_ptr : 3;
    const int idx = indices[n];
    const float* W = weight + (((size_t)idx * N_TILES + t) * C_IN) * C_OUT; // [K][N]

    __shared__ float tile[32][33];
    const int tx = threadIdx.x;   // 0..31
    const int ty = threadIdx.y;   // 0..7
    const int kt = blockIdx.y * 32;
    const int nt = blockIdx.x * 32;

    #pragma unroll
    for (int j = 0; j < 4; j++) {
        const int k = kt + ty + j * 8;
        tile[ty + j * 8][tx] = W[(size_t)k * C_OUT + nt + tx];
    }
    __syncthreads();

    __nv_bfloat16* oh = g_wt_h + (size_t)n * C_OUT * C_IN;
    __nv_bfloat16* ol = g_wt_l + (size_t)n * C_OUT * C_IN;
    #pragma unroll
    for (int j = 0; j < 4; j++) {
        const int nn = nt + ty + j * 8;
        const float v = tile[tx][ty + j * 8];   // = W[kt+tx][nn]
        const __nv_bfloat16 h = __float2bfloat16_rn(v);
        const __nv_bfloat16 l = __float2bfloat16_rn(v - __bfloat162float(h));
        oh[(size_t)nn * C_IN + kt + tx] = h;
        ol[(size_t)nn * C_IN + kt + tx] = l;
    }
}

// ---------------- kernel 2: pipelined bf16 mma.sync GEMM (3-term split) ----------------
__global__ __launch_bounds__(256, 2)
void gemm_bf16_kernel(const float* __restrict__ x,
                      const float* __restrict__ bias,
                      const int* __restrict__ indices,
                      const int* __restrict__ t_ptr,
                      float* __restrict__ out) {
    extern __shared__ __align__(16) unsigned char smem[];
    const uint32_t sa = smem_u32(smem);

    const int tid  = threadIdx.x;
    const int lane = tid & 31;
    const int wid  = tid >> 5;

    const int n_sel  = blockIdx.z;
    const int m0     = blockIdx.x * BM;
    const int n_base = blockIdx.y * BN;
    const int t   = (t_ptr != nullptr) ? *t_ptr : 3;
    const int idx = indices[n_sel];

    const float* A = x + (size_t)n_sel * N_PTS * C_IN + (size_t)m0 * C_IN;
    const __nv_bfloat16* BH = g_wt_h + (size_t)n_sel * C_OUT * C_IN + (size_t)n_base * C_IN;
    const __nv_bfloat16* BL = g_wt_l + (size_t)n_sel * C_OUT * C_IN + (size_t)n_base * C_IN;

    // bias -> smem
    float* bs = (float*)(smem + SM_BIAS);
    if (tid < C_OUT) bs[tid] = bias[((size_t)idx * N_TILES + t) * C_OUT + n_base + tid];

    // warp tiling: 2 m-warps x 4 n-warps; warp tile 64x32
    const int m_off = (wid >> 2) * 64;
    const int n_off = (wid & 3) * 32;

    float acc[4][4][4];
    #pragma unroll
    for (int i = 0; i < 4; i++)
        #pragma unroll
        for (int j = 0; j < 4; j++)
            #pragma unroll
            for (int q = 0; q < 4; q++)
                acc[i][j][q] = 0.0f;

    // ---- async-copy issue for one slab ----
    auto issue_slab = [&](int s) {
        const int stg = s & 1;
        const int k0  = s * BK;
        // A raw fp32: 128 rows x 128B = 1024 x 16B chunks
        #pragma unroll
        for (int i = 0; i < 4; i++) {
            const int c = tid + i * 256;
            const int r = c >> 3, seg = c & 7;
            cp16(sa + SM_ARAW + stg * ARAW_STG + (uint32_t)(r * ARAWB + seg * 16),
                 A + (size_t)r * C_IN + k0 + seg * 4);
        }
        // B hi/lo: 128 rows x 64B = 512 x 16B chunks each
        #pragma unroll
        for (int i = 0; i < 2; i++) {
            const int c = tid + i * 256;
            const int r = c >> 2, seg = c & 3;
            const size_t   go = (size_t)r * C_IN + k0 + seg * 8;
            const uint32_t so = (uint32_t)(r * ROWB + seg * 16);
            cp16(sa + SM_BH + stg * B_STG + so, BH + go);
            cp16(sa + SM_BL + stg * B_STG + so, BL + go);
        }
        asm volatile("cp.async.commit_group;" ::: "memory");
    };

    issue_slab(0);

    for (int s = 0; s < NSLABS; s++) {
        const int stg = s & 1;

        if (s + 1 < NSLABS) {
            issue_slab(s + 1);
            asm volatile("cp.async.wait_group 1;" ::: "memory");
        } else {
            asm volatile("cp.async.wait_group 0;" ::: "memory");
        }
        __syncthreads();   // slab s data visible CTA-wide

        // ---- convert A raw (stage stg) -> Ah/Al (single buffer) ----
        {
            const int r = tid >> 1, half = tid & 1;
            const float4* src = reinterpret_cast<const float4*>(
                smem + SM_ARAW + stg * ARAW_STG + r * ARAWB + half * 64);
            uint32_t h[8], l[8];
            #pragma unroll
            for (int v = 0; v < 4; v++) {
                const float4 f = src[v];
                bf16_split2(f.x, f.y, h[v * 2], l[v * 2]);
                bf16_split2(f.z, f.w, h[v * 2 + 1], l[v * 2 + 1]);
            }
            const uint32_t so = (uint32_t)(r * ROWB + half * 32);
            *reinterpret_cast<uint4*>(smem + SM_AH + so)      = make_uint4(h[0], h[1], h[2], h[3]);
            *reinterpret_cast<uint4*>(smem + SM_AH + so + 16) = make_uint4(h[4], h[5], h[6], h[7]);
            *reinterpret_cast<uint4*>(smem + SM_AL + so)      = make_uint4(l[0], l[1], l[2], l[3]);
            *reinterpret_cast<uint4*>(smem + SM_AL + so + 16) = make_uint4(l[4], l[5], l[6], l[7]);
        }
        __syncthreads();

        // ---- compute: two k-steps of 16 ----
        const uint32_t ahB = sa + SM_AH;
        const uint32_t alB = sa + SM_AL;
        const uint32_t bhB = sa + SM_BH + stg * B_STG;
        const uint32_t blB = sa + SM_BL + stg * B_STG;

        #pragma unroll
        for (int ks = 0; ks < BK; ks += 16) {
            uint32_t bh[4][2], bl[4][2];
            #pragma unroll
            for (int p = 0; p < 2; p++) {
                const int quad = lane >> 3;
                const int rowB = n_off + p * 16 + ((quad >> 1) & 1) * 8 + (lane & 7);
                const int colB = ks + (quad & 1) * 8;
                const uint32_t off = (uint32_t)(rowB * ROWB + colB * 2);
                ldmx4(bhB + off, bh[2 * p][0], bh[2 * p][1], bh[2 * p + 1][0], bh[2 * p + 1][1]);
                ldmx4(blB + off, bl[2 * p][0], bl[2 * p][1], bl[2 * p + 1][0], bl[2 * p + 1][1]);
            }
            #pragma unroll
            for (int mf = 0; mf < 4; mf++) {
                const int rowA = m_off + mf * 16 + (lane & 15);
                const int colA = ks + ((lane >> 4) & 1) * 8;
                const uint32_t off = (uint32_t)(rowA * ROWB + colA * 2);
                uint32_t ah[4], al[4];
                ldmx4(ahB + off, ah[0], ah[1], ah[2], ah[3]);
                ldmx4(alB + off, al[0], al[1], al[2], al[3]);
                #pragma unroll
                for (int nf = 0; nf < 4; nf++) {
                    mma_bf16(acc[mf][nf], ah, bh[nf]);
                    mma_bf16(acc[mf][nf], ah, bl[nf]);
                    mma_bf16(acc[mf][nf], al, bh[nf]);
                }
            }
        }
        __syncthreads();   // protect stage reuse by next issue + Ah/Al rewrite
    }

    // ---- epilogue: + bias, float2 stores ----
    float* Out = out + (size_t)n_sel * N_PTS * C_OUT + (size_t)m0 * C_OUT;
    const int r4 = lane >> 2;
    const int c2 = (lane & 3) * 2;
    #pragma unroll
    for (int mf = 0; mf < 4; mf++) {
        #pragma unroll
        for (int nf = 0; nf < 4; nf++) {
            const int col  = n_off + nf * 8 + c2;
            const int gcol = n_base + col;
            const float bx = bs[col], by = bs[col + 1];
            const int row0 = m_off + mf * 16 + r4;
            float2 o0, o1;
            o0.x = acc[mf][nf][0] + bx; o0.y = acc[mf][nf][1] + by;
            o1.x = acc[mf][nf][2] + bx; o1.y = acc[mf][nf][3] + by;
            *reinterpret_cast<float2*>(Out + (size_t)row0 * C_OUT + gcol) = o0;
            *reinterpret_cast<float2*>(Out + (size_t)(row0 + 8) * C_OUT + gcol) = o1;
        }
    }
}

extern "C" void kernel_launch(void* const* d_in, const int* in_sizes, int n_in,
                              void* d_out, int out_size) {
    const float* x       = (const float*)d_in[0];
    const float* weight  = (const float*)d_in[1];
    const float* bias    = (const float*)d_in[2];
    const int*   indices = (const int*)d_in[3];
    const int*   t_ptr   = (n_in > 4) ? (const int*)d_in[4] : nullptr;
    float*       out     = (float*)d_out;

    {
        dim3 grid(C_OUT / 32, C_IN / 32, N_SEL);
        dim3 block(32, 8);
        wt_prep_kernel<<<grid, block>>>(weight, indices, t_ptr);
    }
    {
        cudaFuncSetAttribute(gemm_bf16_kernel,
                             cudaFuncAttributeMaxDynamicSharedMemorySize, SM_TOTAL);
        dim3 grid(N_PTS / BM, C_OUT / BN, N_SEL);   // (16, 2, 192)
        dim3 block(256);
        gemm_bf16_kernel<<<grid, block, SM_TOTAL>>>(x, bias, indices, t_ptr, out);
    }
}

// round 5
// speedup vs baseline: 2.9393x; 2.9393x over previous
#include <cuda_runtime.h>
#include <cuda_fp16.h>
#include <cstdint>

#define N_SEL   192
#define N_PTS   2048
#define C_IN    256
#define C_OUT   256
#define N_TILES 8

#define BM 128
#define BN 256
#define BK 32
#define NSLABS (C_IN / BK)   // 8
#define THREADS 512

#define ROWB   80            // tile row bytes: 32 fp16 (64B) + 16 pad

// dynamic smem layout
#define SM_BIAS  0                         // 256 f32 = 1024 B
#define SM_AH    1024                      // 2 stages x 128 rows x 80 B
#define A_STG    (BM * ROWB)               // 10240
#define SM_B     (SM_AH + 2 * A_STG)       // 21504; 3 stages x 256 rows x 80 B
#define B_STG    (BN * ROWB)               // 20480
#define SM_TOTAL (SM_B + 3 * B_STG)        // 82944

// gathered, transposed fp16 weights: [n_sel][N=C_OUT][K=C_IN]
__device__ __half g_wt[(size_t)N_SEL * C_OUT * C_IN];

__device__ __forceinline__ uint32_t smem_u32(const void* p) {
    uint32_t a;
    asm("{ .reg .u64 t; cvta.to.shared.u64 t, %1; cvt.u32.u64 %0, t; }" : "=r"(a) : "l"(p));
    return a;
}
__device__ __forceinline__ void cp16(uint32_t dst, const void* src) {
    asm volatile("cp.async.cg.shared.global [%0], [%1], 16;" :: "r"(dst), "l"(src));
}
__device__ __forceinline__ uint32_t pack_h2(float a, float b) {
    uint32_t r;
    asm("cvt.rn.f16x2.f32 %0, %2, %1;" : "=r"(r) : "f"(a), "f"(b));
    return r;
}
__device__ __forceinline__ void ldmx4(uint32_t addr, uint32_t& r0, uint32_t& r1,
                                      uint32_t& r2, uint32_t& r3) {
    asm volatile("ldmatrix.sync.aligned.m8n8.x4.shared.b16 {%0,%1,%2,%3}, [%4];"
                 : "=r"(r0), "=r"(r1), "=r"(r2), "=r"(r3) : "r"(addr));
}
__device__ __forceinline__ void mma_f16(float* c, const uint32_t* a, const uint32_t* b) {
    asm volatile("mma.sync.aligned.m16n8k16.row.col.f32.f16.f16.f32 "
                 "{%0,%1,%2,%3}, {%4,%5,%6,%7}, {%8,%9}, {%0,%1,%2,%3};"
                 : "+f"(c[0]), "+f"(c[1]), "+f"(c[2]), "+f"(c[3])
                 : "r"(a[0]), "r"(a[1]), "r"(a[2]), "r"(a[3]), "r"(b[0]), "r"(b[1]));
}

// ---------------- kernel 1: gather + transpose + fp16 convert of W ----------------
__global__ void wt_prep_kernel(const float* __restrict__ weight,
                               const int* __restrict__ indices,
                               const int* __restrict__ t_ptr) {
    const int n = blockIdx.z;
    const int t = (t_ptr != nullptr) ? *t_ptr : 3;
    const int idx = indices[n];
    const float* W = weight + (((size_t)idx * N_TILES + t) * C_IN) * C_OUT; // [K][N]

    __shared__ float tile[32][33];
    const int tx = threadIdx.x;   // 0..31
    const int ty = threadIdx.y;   // 0..7
    const int kt = blockIdx.y * 32;
    const int nt = blockIdx.x * 32;

    #pragma unroll
    for (int j = 0; j < 4; j++) {
        const int k = kt + ty + j * 8;
        tile[ty + j * 8][tx] = W[(size_t)k * C_OUT + nt + tx];
    }
    __syncthreads();

    __half* o = g_wt + (size_t)n * C_OUT * C_IN;
    #pragma unroll
    for (int j = 0; j < 4; j++) {
        const int nn = nt + ty + j * 8;
        o[(size_t)nn * C_IN + kt + tx] = __float2half_rn(tile[tx][ty + j * 8]);
    }
}

// ---------------- kernel 2: single-pass fp16 mma.sync GEMM ----------------
__global__ __launch_bounds__(THREADS, 1)
void gemm_f16_kernel(const float* __restrict__ x,
                     const float* __restrict__ bias,
                     const int* __restrict__ indices,
                     const int* __restrict__ t_ptr,
                     float* __restrict__ out) {
    extern __shared__ __align__(16) unsigned char smem[];
    const uint32_t sa = smem_u32(smem);

    const int tid  = threadIdx.x;
    const int lane = tid & 31;
    const int wid  = tid >> 5;          // 0..15

    const int n_sel = blockIdx.y;
    const int m0    = blockIdx.x * BM;
    const int t   = (t_ptr != nullptr) ? *t_ptr : 3;
    const int idx = indices[n_sel];

    const float* A = x + (size_t)n_sel * N_PTS * C_IN + (size_t)m0 * C_IN;
    const __half* Wn = g_wt + (size_t)n_sel * C_OUT * C_IN;

    // bias -> smem
    float* bs = (float*)(smem + SM_BIAS);
    if (tid < C_OUT) bs[tid] = bias[((size_t)idx * N_TILES + t) * C_OUT + tid];

    // warp tiling: 2 m-warps x 8 n-warps; warp tile 64x32
    const int m_off = (wid >> 3) * 64;
    const int n_off = (wid & 7) * 32;

    float acc[4][4][4];
    #pragma unroll
    for (int i = 0; i < 4; i++)
        #pragma unroll
        for (int j = 0; j < 4; j++)
            #pragma unroll
            for (int q = 0; q < 4; q++)
                acc[i][j][q] = 0.0f;

    // per-thread A load mapping: 512 threads -> 128 rows x 32 cols (8 floats/thread)
    const int ar  = tid >> 2;            // row 0..127
    const int as8 = (tid & 3) * 8;       // col start (floats)

    // B cp.async mapping: 1024 chunks of 16B (256 rows x 4 chunks)
    auto issue_B = [&](int s) {
        const uint32_t base = sa + SM_B + (uint32_t)(s % 3) * B_STG;
        const int k0 = s * BK;
        #pragma unroll
        for (int i = 0; i < 2; i++) {
            const int c = tid + i * THREADS;
            const int r = c >> 2, seg = c & 3;
            cp16(base + (uint32_t)(r * ROWB + seg * 16),
                 Wn + (size_t)r * C_IN + k0 + seg * 8);
        }
        asm volatile("cp.async.commit_group;" ::: "memory");
    };

    // prologue: A slab 0 into regs, B slab 0 in flight
    float4 a0, a1;
    {
        const float* src = A + (size_t)ar * C_IN + as8;
        a0 = *reinterpret_cast<const float4*>(src);
        a1 = *reinterpret_cast<const float4*>(src + 4);
    }
    issue_B(0);

    for (int s = 0; s < NSLABS; s++) {
        const int stgA = s & 1;

        // convert A regs -> fp16 smem (stage stgA)
        {
            const uint32_t so = sa + SM_AH + (uint32_t)(stgA * A_STG + ar * ROWB + (as8 >> 3) * 16);
            uint4 v;
            v.x = pack_h2(a0.x, a0.y);
            v.y = pack_h2(a0.z, a0.w);
            v.z = pack_h2(a1.x, a1.y);
            v.w = pack_h2(a1.z, a1.w);
            *reinterpret_cast<uint4*>((unsigned char*)smem + (so - sa)) = v;
        }

        // prefetch slab s+1
        if (s + 1 < NSLABS) {
            const float* src = A + (size_t)ar * C_IN + (s + 1) * BK + as8;
            a0 = *reinterpret_cast<const float4*>(src);
            a1 = *reinterpret_cast<const float4*>(src + 4);
            issue_B(s + 1);
            asm volatile("cp.async.wait_group 1;" ::: "memory");
        } else {
            asm volatile("cp.async.wait_group 0;" ::: "memory");
        }
        __syncthreads();   // Ah[stgA] + B[s%3] ready; all warps done with prior stages

        const uint32_t aB = sa + SM_AH + (uint32_t)(stgA * A_STG);
        const uint32_t bB = sa + SM_B  + (uint32_t)((s % 3) * B_STG);

        #pragma unroll
        for (int ks = 0; ks < BK; ks += 16) {
            uint32_t bf[4][2];
            #pragma unroll
            for (int p = 0; p < 2; p++) {
                const int quad = lane >> 3;
                const int rowB = n_off + p * 16 + ((quad >> 1) & 1) * 8 + (lane & 7);
                const int colB = ks + (quad & 1) * 8;
                ldmx4(bB + (uint32_t)(rowB * ROWB + colB * 2),
                      bf[2 * p][0], bf[2 * p][1], bf[2 * p + 1][0], bf[2 * p + 1][1]);
            }
            #pragma unroll
            for (int mf = 0; mf < 4; mf++) {
                const int rowA = m_off + mf * 16 + (lane & 15);
                const int colA = ks + ((lane >> 4) & 1) * 8;
                uint32_t af[4];
                ldmx4(aB + (uint32_t)(rowA * ROWB + colA * 2), af[0], af[1], af[2], af[3]);
                #pragma unroll
                for (int nf = 0; nf < 4; nf++)
                    mma_f16(acc[mf][nf], af, bf[nf]);
            }
        }
        // no trailing sync: next iter writes other A stage / B stage (s+2)%3,
        // and the next __syncthreads orders all readers before any overwrite
        // of a stage that could still be in use two iterations out.
    }

    // ---- epilogue: + bias, float2 stores ----
    float* Out = out + (size_t)n_sel * N_PTS * C_OUT + (size_t)m0 * C_OUT;
    const int r4 = lane >> 2;
    const int c2 = (lane & 3) * 2;
    #pragma unroll
    for (int mf = 0; mf < 4; mf++) {
        #pragma unroll
        for (int nf = 0; nf < 4; nf++) {
            const int col = n_off + nf * 8 + c2;
            const float bx = bs[col], by = bs[col + 1];
            const int row0 = m_off + mf * 16 + r4;
            float2 o0, o1;
            o0.x = acc[mf][nf][0] + bx; o0.y = acc[mf][nf][1] + by;
            o1.x = acc[mf][nf][2] + bx; o1.y = acc[mf][nf][3] + by;
            *reinterpret_cast<float2*>(Out + (size_t)row0 * C_OUT + col) = o0;
            *reinterpret_cast<float2*>(Out + (size_t)(row0 + 8) * C_OUT + col) = o1;
        }
    }
}

extern "C" void kernel_launch(void* const* d_in, const int* in_sizes, int n_in,
                              void* d_out, int out_size) {
    const float* x       = (const float*)d_in[0];
    const float* weight  = (const float*)d_in[1];
    const float* bias    = (const float*)d_in[2];
    const int*   indices = (const int*)d_in[3];
    const int*   t_ptr   = (n_in > 4) ? (const int*)d_in[4] : nullptr;
    float*       out     = (float*)d_out;

    {
        dim3 grid(C_OUT / 32, C_IN / 32, N_SEL);
        dim3 block(32, 8);
        wt_prep_kernel<<<grid, block>>>(weight, indices, t_ptr);
    }
    {
        cudaFuncSetAttribute(gemm_f16_kernel,
                             cudaFuncAttributeMaxDynamicSharedMemorySize, SM_TOTAL);
        dim3 grid(N_PTS / BM, N_SEL);   // (16, 192)
        dim3 block(THREADS);
        gemm_f16_kernel<<<grid, block, SM_TOTAL>>>(x, bias, indices, t_ptr, out);
    }
}

// round 6
// speedup vs baseline: 3.1032x; 1.0557x over previous
#include <cuda_runtime.h>
#include <cuda_fp16.h>
#include <cstdint>

#define N_SEL   192
#define N_PTS   2048
#define C_IN    256
#define C_OUT   256
#define N_TILES 8

#define BM 64
#define BN 256
#define BK 32
#define NSLABS (C_IN / BK)   // 8
#define THREADS 256

#define ROWB   80            // tile row bytes: 32 fp16 (64B) + 16 pad

// dynamic smem layout
#define SM_BIAS  0                         // 256 f32 = 1024 B
#define SM_AH    1024                      // 2 stages x 64 rows x 80 B
#define A_STG    (BM * ROWB)               // 5120
#define SM_B     (SM_AH + 2 * A_STG)       // 11264; 3 stages x 256 rows x 80 B
#define B_STG    (BN * ROWB)               // 20480
#define SM_TOTAL (SM_B + 3 * B_STG)        // 72704

// gathered, transposed fp16 weights: [n_sel][N=C_OUT][K=C_IN]
__device__ __half g_wt[(size_t)N_SEL * C_OUT * C_IN];

__device__ __forceinline__ uint32_t smem_u32(const void* p) {
    uint32_t a;
    asm("{ .reg .u64 t; cvta.to.shared.u64 t, %1; cvt.u32.u64 %0, t; }" : "=r"(a) : "l"(p));
    return a;
}
__device__ __forceinline__ void cp16(uint32_t dst, const void* src) {
    asm volatile("cp.async.cg.shared.global [%0], [%1], 16;" :: "r"(dst), "l"(src));
}
__device__ __forceinline__ uint32_t pack_h2(float a, float b) {
    uint32_t r;
    asm("cvt.rn.f16x2.f32 %0, %2, %1;" : "=r"(r) : "f"(a), "f"(b));
    return r;
}
__device__ __forceinline__ void ldmx4(uint32_t addr, uint32_t& r0, uint32_t& r1,
                                      uint32_t& r2, uint32_t& r3) {
    asm volatile("ldmatrix.sync.aligned.m8n8.x4.shared.b16 {%0,%1,%2,%3}, [%4];"
                 : "=r"(r0), "=r"(r1), "=r"(r2), "=r"(r3) : "r"(addr));
}
__device__ __forceinline__ void mma_f16(float* c, const uint32_t* a, const uint32_t* b) {
    asm volatile("mma.sync.aligned.m16n8k16.row.col.f32.f16.f16.f32 "
                 "{%0,%1,%2,%3}, {%4,%5,%6,%7}, {%8,%9}, {%0,%1,%2,%3};"
                 : "+f"(c[0]), "+f"(c[1]), "+f"(c[2]), "+f"(c[3])
                 : "r"(a[0]), "r"(a[1]), "r"(a[2]), "r"(a[3]), "r"(b[0]), "r"(b[1]));
}

// ---------------- kernel 1: gather + transpose + fp16 convert of W ----------------
__global__ void wt_prep_kernel(const float* __restrict__ weight,
                               const int* __restrict__ indices,
                               const int* __restrict__ t_ptr) {
    const int n = blockIdx.z;
    const int t = (t_ptr != nullptr) ? *t_ptr : 3;
    const int idx = indices[n];
    const float* W = weight + (((size_t)idx * N_TILES + t) * C_IN) * C_OUT; // [K][N]

    __shared__ float tile[32][33];
    const int tx = threadIdx.x;   // 0..31
    const int ty = threadIdx.y;   // 0..7
    const int kt = blockIdx.y * 32;
    const int nt = blockIdx.x * 32;

    #pragma unroll
    for (int j = 0; j < 4; j++) {
        const int k = kt + ty + j * 8;
        tile[ty + j * 8][tx] = W[(size_t)k * C_OUT + nt + tx];
    }
    __syncthreads();

    __half* o = g_wt + (size_t)n * C_OUT * C_IN;
    #pragma unroll
    for (int j = 0; j < 4; j++) {
        const int nn = nt + ty + j * 8;
        o[(size_t)nn * C_IN + kt + tx] = __float2half_rn(tile[tx][ty + j * 8]);
    }
}

// ---------------- kernel 2: single-pass fp16 mma.sync GEMM, 2 CTAs/SM ----------------
__global__ __launch_bounds__(THREADS, 2)
void gemm_f16_kernel(const float* __restrict__ x,
                     const float* __restrict__ bias,
                     const int* __restrict__ indices,
                     const int* __restrict__ t_ptr,
                     float* __restrict__ out) {
    extern __shared__ __align__(16) unsigned char smem[];
    const uint32_t sa = smem_u32(smem);

    const int tid  = threadIdx.x;
    const int lane = tid & 31;
    const int wid  = tid >> 5;          // 0..7

    const int n_sel = blockIdx.y;
    const int m0    = blockIdx.x * BM;
    const int t   = (t_ptr != nullptr) ? *t_ptr : 3;
    const int idx = indices[n_sel];

    const float* A = x + (size_t)n_sel * N_PTS * C_IN + (size_t)m0 * C_IN;
    const __half* Wn = g_wt + (size_t)n_sel * C_OUT * C_IN;

    // bias -> smem
    float* bs = (float*)(smem + SM_BIAS);
    if (tid < C_OUT) bs[tid] = bias[((size_t)idx * N_TILES + t) * C_OUT + tid];

    // warp tiling: 2 m-warps x 4 n-warps; warp tile 32x64
    const int m_off = (wid >> 2) * 32;
    const int n_off = (wid & 3) * 64;

    float acc[2][8][4];
    #pragma unroll
    for (int i = 0; i < 2; i++)
        #pragma unroll
        for (int j = 0; j < 8; j++)
            #pragma unroll
            for (int q = 0; q < 4; q++)
                acc[i][j][q] = 0.0f;

    // per-thread A load mapping: 256 threads -> 64 rows x 32 cols (8 floats/thread)
    const int ar  = tid >> 2;            // row 0..63
    const int as8 = (tid & 3) * 8;       // col start (floats)

    // B cp.async mapping: 1024 chunks of 16B (256 rows x 4 chunks)
    auto issue_B = [&](int s) {
        const uint32_t base = sa + SM_B + (uint32_t)(s % 3) * B_STG;
        const int k0 = s * BK;
        #pragma unroll
        for (int i = 0; i < 4; i++) {
            const int c = tid + i * THREADS;
            const int r = c >> 2, seg = c & 3;
            cp16(base + (uint32_t)(r * ROWB + seg * 16),
                 Wn + (size_t)r * C_IN + k0 + seg * 8);
        }
        asm volatile("cp.async.commit_group;" ::: "memory");
    };

    // prologue: A slab 0 into regs, B slab 0 in flight
    float4 a0, a1;
    {
        const float* src = A + (size_t)ar * C_IN + as8;
        a0 = *reinterpret_cast<const float4*>(src);
        a1 = *reinterpret_cast<const float4*>(src + 4);
    }
    issue_B(0);

    for (int s = 0; s < NSLABS; s++) {
        const int stgA = s & 1;

        // convert A regs -> fp16 smem (stage stgA)
        {
            const uint32_t off = (uint32_t)(SM_AH + stgA * A_STG + ar * ROWB + (as8 >> 3) * 16);
            uint4 v;
            v.x = pack_h2(a0.x, a0.y);
            v.y = pack_h2(a0.z, a0.w);
            v.z = pack_h2(a1.x, a1.y);
            v.w = pack_h2(a1.z, a1.w);
            *reinterpret_cast<uint4*>(smem + off) = v;
        }

        // prefetch slab s+1
        if (s + 1 < NSLABS) {
            const float* src = A + (size_t)ar * C_IN + (s + 1) * BK + as8;
            a0 = *reinterpret_cast<const float4*>(src);
            a1 = *reinterpret_cast<const float4*>(src + 4);
            issue_B(s + 1);
            asm volatile("cp.async.wait_group 1;" ::: "memory");
        } else {
            asm volatile("cp.async.wait_group 0;" ::: "memory");
        }
        __syncthreads();   // Ah[stgA] + B[s%3] ready; all warps done with prior stages

        const uint32_t aB = sa + SM_AH + (uint32_t)(stgA * A_STG);
        const uint32_t bB = sa + SM_B  + (uint32_t)((s % 3) * B_STG);

        #pragma unroll
        for (int ks = 0; ks < BK; ks += 16) {
            uint32_t bf[8][2];
            #pragma unroll
            for (int p = 0; p < 4; p++) {
                const int quad = lane >> 3;
                const int rowB = n_off + p * 16 + ((quad >> 1) & 1) * 8 + (lane & 7);
                const int colB = ks + (quad & 1) * 8;
                ldmx4(bB + (uint32_t)(rowB * ROWB + colB * 2),
                      bf[2 * p][0], bf[2 * p][1], bf[2 * p + 1][0], bf[2 * p + 1][1]);
            }
            #pragma unroll
            for (int mf = 0; mf < 2; mf++) {
                const int rowA = m_off + mf * 16 + (lane & 15);
                const int colA = ks + ((lane >> 4) & 1) * 8;
                uint32_t af[4];
                ldmx4(aB + (uint32_t)(rowA * ROWB + colA * 2), af[0], af[1], af[2], af[3]);
                #pragma unroll
                for (int nf = 0; nf < 8; nf++)
                    mma_f16(acc[mf][nf], af, bf[nf]);
            }
        }
        // no trailing sync: the next iteration's __syncthreads (after its own
        // wait_group) orders all readers of a stage before any overwrite — the
        // A stage flips every iter and B ring has 3 stages, so the stage being
        // rewritten was last READ one full iteration ago, behind that barrier.
    }

    // ---- epilogue: + bias, float2 stores ----
    float* Out = out + (size_t)n_sel * N_PTS * C_OUT + (size_t)m0 * C_OUT;
    const int r4 = lane >> 2;
    const int c2 = (lane & 3) * 2;
    #pragma unroll
    for (int mf = 0; mf < 2; mf++) {
        #pragma unroll
        for (int nf = 0; nf < 8; nf++) {
            const int col = n_off + nf * 8 + c2;
            const float bx = bs[col], by = bs[col + 1];
            const int row0 = m_off + mf * 16 + r4;
            float2 o0, o1;
            o0.x = acc[mf][nf][0] + bx; o0.y = acc[mf][nf][1] + by;
            o1.x = acc[mf][nf][2] + bx; o1.y = acc[mf][nf][3] + by;
            *reinterpret_cast<float2*>(Out + (size_t)row0 * C_OUT + col) = o0;
            *reinterpret_cast<float2*>(Out + (size_t)(row0 + 8) * C_OUT + col) = o1;
        }
    }
}

extern "C" void kernel_launch(void* const* d_in, const int* in_sizes, int n_in,
                              void* d_out, int out_size) {
    const float* x       = (const float*)d_in[0];
    const float* weight  = (const float*)d_in[1];
    const float* bias    = (const float*)d_in[2];
    const int*   indices = (const int*)d_in[3];
    const int*   t_ptr   = (n_in > 4) ? (const int*)d_in[4] : nullptr;
    float*       out     = (float*)d_out;

    {
        dim3 grid(C_OUT / 32, C_IN / 32, N_SEL);
        dim3 block(32, 8);
        wt_prep_kernel<<<grid, block>>>(weight, indices, t_ptr);
    }
    {
        cudaFuncSetAttribute(gemm_f16_kernel,
                             cudaFuncAttributeMaxDynamicSharedMemorySize, SM_TOTAL);
        dim3 grid(N_PTS / BM, N_SEL);   // (32, 192); m-tiles fastest -> same-n_sel adjacency
        dim3 block(THREADS);
        gemm_f16_kernel<<<grid, block, SM_TOTAL>>>(x, bias, indices, t_ptr, out);
    }
}